// round 1
// baseline (speedup 1.0000x reference)
#include <cuda_runtime.h>

#define NEG_INF_F (-1.0e12f)

constexpr int S_  = 1024;
constexpr int D_  = 128;
constexpr int H_  = 8;
constexpr int BH_ = 32;   // B*H = 4*8

// Scratch: attention scores / probabilities, 32 * 1024 * 1024 fp32 = 134 MB.
static __device__ float g_scores[(size_t)BH_ * S_ * S_];

// ---------------------------------------------------------------------------
// Kernel 1: scores[bh,i,j] = mask ? scale * dot(q[bh,i,:], k[bh,j,:]) : -1e12
// 64x64 tile per block, BK=64 (two chunks over D=128), 4x4 register micro-tile.
// ---------------------------------------------------------------------------
__global__ void __launch_bounds__(256) qk_kernel(const float* __restrict__ q,
                                                 const float* __restrict__ k,
                                                 const int*   __restrict__ mask) {
    __shared__ float qs[64][68];   // [kx][m], pad 4 keeps float4 alignment
    __shared__ float ks[64][68];   // [kx][n]

    const int bh   = blockIdx.z;
    const int b    = bh >> 3;      // H_ = 8
    const int row0 = blockIdx.y << 6;
    const int col0 = blockIdx.x << 6;
    const int tid  = threadIdx.x;
    const int ty   = tid >> 4;
    const int tx   = tid & 15;

    float acc[4][4] = {};

    const float* qbase = q + (size_t)bh * S_ * D_;
    const float* kbase = k + (size_t)bh * S_ * D_;

    for (int kb = 0; kb < D_; kb += 64) {
        #pragma unroll
        for (int l = 0; l < 4; ++l) {
            int idx = tid + (l << 8);       // 0..1023 float4 slots
            int r   = idx >> 4;             // row within tile
            int c   = (idx & 15) << 2;      // k-col within chunk
            float4 vq = *(const float4*)(qbase + (size_t)(row0 + r) * D_ + kb + c);
            qs[c + 0][r] = vq.x; qs[c + 1][r] = vq.y;
            qs[c + 2][r] = vq.z; qs[c + 3][r] = vq.w;
            float4 vk = *(const float4*)(kbase + (size_t)(col0 + r) * D_ + kb + c);
            ks[c + 0][r] = vk.x; ks[c + 1][r] = vk.y;
            ks[c + 2][r] = vk.z; ks[c + 3][r] = vk.w;
        }
        __syncthreads();

        #pragma unroll 16
        for (int kx = 0; kx < 64; ++kx) {
            float4 a  = *(const float4*)&qs[kx][ty << 2];
            float4 bb = *(const float4*)&ks[kx][tx << 2];
            float av[4] = {a.x, a.y, a.z, a.w};
            float bv[4] = {bb.x, bb.y, bb.z, bb.w};
            #pragma unroll
            for (int i = 0; i < 4; ++i)
                #pragma unroll
                for (int j = 0; j < 4; ++j)
                    acc[i][j] = fmaf(av[i], bv[j], acc[i][j]);
        }
        __syncthreads();
    }

    const float scale = 0.08838834764831845f;  // 1/sqrt(128)
    float*     srow = g_scores + (size_t)bh * S_ * S_;
    const int* mrow = mask     + (size_t)b  * S_ * S_;

    #pragma unroll
    for (int i = 0; i < 4; ++i) {
        int ii = row0 + (ty << 2) + i;
        int jj = col0 + (tx << 2);
        int4 mk = *(const int4*)(mrow + (size_t)ii * S_ + jj);
        float4 o;
        o.x = mk.x ? acc[i][0] * scale : NEG_INF_F;
        o.y = mk.y ? acc[i][1] * scale : NEG_INF_F;
        o.z = mk.z ? acc[i][2] * scale : NEG_INF_F;
        o.w = mk.w ? acc[i][3] * scale : NEG_INF_F;
        *(float4*)(srow + (size_t)ii * S_ + jj) = o;
    }
}

// ---------------------------------------------------------------------------
// Kernel 2: in-place entmax-1.5 over each 1024-element row of g_scores.
// x = (s - rowmax)/2; find tau with sum(max(x-tau,0)^2) = 1 via safeguarded
// Newton (monotone from below by convexity); p = max(x-tau,0)^2.
// One block (256 threads) per row; row lives in 4 registers per thread.
// ---------------------------------------------------------------------------
__global__ void __launch_bounds__(256) entmax_kernel() {
    __shared__ float sm[16];

    const size_t row  = blockIdx.x;
    float4*      rowp = (float4*)(g_scores + row * S_);
    const int    tid  = threadIdx.x;
    const int    lane = tid & 31;
    const int    wid  = tid >> 5;

    float4 xv = rowp[tid];

    // row max
    float m = fmaxf(fmaxf(xv.x, xv.y), fmaxf(xv.z, xv.w));
    #pragma unroll
    for (int o = 16; o; o >>= 1) m = fmaxf(m, __shfl_xor_sync(0xffffffffu, m, o));
    if (lane == 0) sm[wid] = m;
    __syncthreads();
    float rowmax = sm[0];
    #pragma unroll
    for (int w = 1; w < 8; ++w) rowmax = fmaxf(rowmax, sm[w]);
    __syncthreads();

    float x0 = (xv.x - rowmax) * 0.5f;
    float x1 = (xv.y - rowmax) * 0.5f;
    float x2 = (xv.z - rowmax) * 0.5f;
    float x3 = (xv.w - rowmax) * 0.5f;

    // Newton on f(tau) = sum clip(x - tau)^2 - 1. Root tau* in [-1, -1/32].
    float tau = -1.0f;
    for (int it = 0; it < 20; ++it) {
        float t0 = fmaxf(x0 - tau, 0.0f);
        float t1 = fmaxf(x1 - tau, 0.0f);
        float t2 = fmaxf(x2 - tau, 0.0f);
        float t3 = fmaxf(x3 - tau, 0.0f);
        float s1 = (t0 + t1) + (t2 + t3);
        float s2 = fmaf(t0, t0, t1 * t1) + fmaf(t2, t2, t3 * t3);
        #pragma unroll
        for (int o = 16; o; o >>= 1) {
            s1 += __shfl_xor_sync(0xffffffffu, s1, o);
            s2 += __shfl_xor_sync(0xffffffffu, s2, o);
        }
        if (lane == 0) { sm[wid] = s1; sm[8 + wid] = s2; }
        __syncthreads();
        float S1 = 0.0f, S2 = 0.0f;
        #pragma unroll
        for (int w = 0; w < 8; ++w) { S1 += sm[w]; S2 += sm[8 + w]; }
        __syncthreads();
        tau += (S2 - 1.0f) / (2.0f * S1);
        tau  = fminf(tau, -0.03125f);   // tau* <= -1/32 provably; keeps S1 > 0
        if (fabsf(S2 - 1.0f) < 1e-7f) break;   // uniform across block
    }

    float t0 = fmaxf(x0 - tau, 0.0f);
    float t1 = fmaxf(x1 - tau, 0.0f);
    float t2 = fmaxf(x2 - tau, 0.0f);
    float t3 = fmaxf(x3 - tau, 0.0f);
    rowp[tid] = make_float4(t0 * t0, t1 * t1, t2 * t2, t3 * t3);
}

// ---------------------------------------------------------------------------
// Kernel 3: out[bh,i,d] = sum_j p[bh,i,j] * v[bh,j,d]
// 64(M) x 64(N) tile, BK=64 over the 1024 keys.
// ---------------------------------------------------------------------------
__global__ void __launch_bounds__(256) pv_kernel(const float* __restrict__ v,
                                                 float* __restrict__ out) {
    __shared__ float ps[64][68];   // [kx][m]
    __shared__ float vs[64][64];   // [kx][n]

    const int bh   = blockIdx.z;
    const int row0 = blockIdx.y << 6;
    const int col0 = blockIdx.x << 6;   // 0 or 64 within D
    const int tid  = threadIdx.x;
    const int ty   = tid >> 4;
    const int tx   = tid & 15;

    float acc[4][4] = {};

    const float* pbase = g_scores + (size_t)bh * S_ * S_;
    const float* vbase = v        + (size_t)bh * S_ * D_;

    for (int kb = 0; kb < S_; kb += 64) {
        #pragma unroll
        for (int l = 0; l < 4; ++l) {
            int idx = tid + (l << 8);
            int r   = idx >> 4;
            int c   = (idx & 15) << 2;
            float4 vp = *(const float4*)(pbase + (size_t)(row0 + r) * S_ + kb + c);
            ps[c + 0][r] = vp.x; ps[c + 1][r] = vp.y;
            ps[c + 2][r] = vp.z; ps[c + 3][r] = vp.w;
            float4 vv = *(const float4*)(vbase + (size_t)(kb + r) * D_ + col0 + c);
            *(float4*)&vs[r][c] = vv;
        }
        __syncthreads();

        #pragma unroll 16
        for (int kx = 0; kx < 64; ++kx) {
            float4 a  = *(const float4*)&ps[kx][ty << 2];
            float4 bb = *(const float4*)&vs[kx][tx << 2];
            float av[4] = {a.x, a.y, a.z, a.w};
            float bv[4] = {bb.x, bb.y, bb.z, bb.w};
            #pragma unroll
            for (int i = 0; i < 4; ++i)
                #pragma unroll
                for (int j = 0; j < 4; ++j)
                    acc[i][j] = fmaf(av[i], bv[j], acc[i][j]);
        }
        __syncthreads();
    }

    #pragma unroll
    for (int i = 0; i < 4; ++i) {
        int ii = row0 + (ty << 2) + i;
        int dd = col0 + (tx << 2);
        float4 o = make_float4(acc[i][0], acc[i][1], acc[i][2], acc[i][3]);
        *(float4*)(out + ((size_t)bh * S_ + ii) * D_ + dd) = o;
    }
}

// ---------------------------------------------------------------------------
extern "C" void kernel_launch(void* const* d_in, const int* in_sizes, int n_in,
                              void* d_out, int out_size) {
    (void)in_sizes; (void)n_in; (void)out_size;
    const float* q    = (const float*)d_in[0];
    const float* k    = (const float*)d_in[1];
    const float* v    = (const float*)d_in[2];
    const int*   mask = (const int*)d_in[3];
    float*       out  = (float*)d_out;

    qk_kernel<<<dim3(16, 16, BH_), 256>>>(q, k, mask);
    entmax_kernel<<<BH_ * S_, 256>>>();
    pv_kernel<<<dim3(D_ / 64, 16, BH_), 256>>>(v, out);
}

// round 2
// speedup vs baseline: 1.2307x; 1.2307x over previous
#include <cuda_runtime.h>

#define NEG_INF_F (-1.0e12f)

constexpr int S_  = 1024;
constexpr int D_  = 128;
constexpr int BH_ = 32;   // B*H = 4*8

// Scratch: masked+scaled scores (134 MB) and per-row entmax threshold.
static __device__ float g_scores[(size_t)BH_ * S_ * S_];
static __device__ float g_thresh[(size_t)BH_ * S_];   // rowmax + 2*tau

// ---------------------------------------------------------------------------
// Kernel 1: scores = mask ? scale * Q K^T : -1e12
// 128x128 tile, BK=8, 256 threads, 8x8 register micro-tile, gmem prefetch.
// ---------------------------------------------------------------------------
__global__ void __launch_bounds__(256) qk_kernel(const float* __restrict__ q,
                                                 const float* __restrict__ k,
                                                 const int*   __restrict__ mask) {
    __shared__ float qs[8][132];   // [kx][m], 132 = pad (33 float4 per row)
    __shared__ float ks[8][132];   // [kx][n]

    const int tid  = threadIdx.x;
    const int bh   = blockIdx.z;
    const int b    = bh >> 3;
    const int row0 = blockIdx.y << 7;
    const int col0 = blockIdx.x << 7;
    const int ty   = tid >> 4;        // 0..15
    const int tx   = tid & 15;        // 0..15
    const int lr   = tid >> 1;        // 0..127 (tile row to load)
    const int lc   = (tid & 1) << 2;  // 0 or 4 (k-col within chunk)

    const float* qp = q + ((size_t)bh * S_ + row0 + lr) * D_ + lc;
    const float* kp = k + ((size_t)bh * S_ + col0 + lr) * D_ + lc;

    float4 qreg = *(const float4*)qp;
    float4 kreg = *(const float4*)kp;

    float acc[8][8] = {};

    for (int kb = 0; kb < D_; kb += 8) {
        qs[lc + 0][lr] = qreg.x; qs[lc + 1][lr] = qreg.y;
        qs[lc + 2][lr] = qreg.z; qs[lc + 3][lr] = qreg.w;
        ks[lc + 0][lr] = kreg.x; ks[lc + 1][lr] = kreg.y;
        ks[lc + 2][lr] = kreg.z; ks[lc + 3][lr] = kreg.w;
        __syncthreads();

        if (kb + 8 < D_) {             // prefetch next chunk during compute
            qreg = *(const float4*)(qp + kb + 8);
            kreg = *(const float4*)(kp + kb + 8);
        }

        #pragma unroll
        for (int kx = 0; kx < 8; ++kx) {
            float4 a0 = *(const float4*)&qs[kx][ty << 2];
            float4 a1 = *(const float4*)&qs[kx][64 + (ty << 2)];
            float4 b0 = *(const float4*)&ks[kx][tx << 2];
            float4 b1 = *(const float4*)&ks[kx][64 + (tx << 2)];
            float av[8] = {a0.x, a0.y, a0.z, a0.w, a1.x, a1.y, a1.z, a1.w};
            float bv[8] = {b0.x, b0.y, b0.z, b0.w, b1.x, b1.y, b1.z, b1.w};
            #pragma unroll
            for (int i = 0; i < 8; ++i)
                #pragma unroll
                for (int j = 0; j < 8; ++j)
                    acc[i][j] = fmaf(av[i], bv[j], acc[i][j]);
        }
        __syncthreads();
    }

    const float scale = 0.08838834764831845f;   // 1/sqrt(128)
    float*     srow = g_scores + (size_t)bh * S_ * S_;
    const int* mrow = mask     + (size_t)b  * S_ * S_;

    #pragma unroll
    for (int rg = 0; rg < 2; ++rg)
        #pragma unroll
        for (int i = 0; i < 4; ++i) {
            int ii = row0 + (rg << 6) + (ty << 2) + i;
            #pragma unroll
            for (int cg = 0; cg < 2; ++cg) {
                int jj = col0 + (cg << 6) + (tx << 2);
                int4 mk = *(const int4*)(mrow + (size_t)ii * S_ + jj);
                float4 o;
                o.x = mk.x ? acc[rg * 4 + i][cg * 4 + 0] * scale : NEG_INF_F;
                o.y = mk.y ? acc[rg * 4 + i][cg * 4 + 1] * scale : NEG_INF_F;
                o.z = mk.z ? acc[rg * 4 + i][cg * 4 + 2] * scale : NEG_INF_F;
                o.w = mk.w ? acc[rg * 4 + i][cg * 4 + 3] * scale : NEG_INF_F;
                *(float4*)(srow + (size_t)ii * S_ + jj) = o;
            }
        }
}

// ---------------------------------------------------------------------------
// Kernel 2: per-row entmax-1.5 threshold only.
// Solve sum(max((s-rowmax)/2 - tau, 0)^2) = 1 by safeguarded Newton; write
// T = rowmax + 2*tau. (Probabilities are reconstructed inside pv_kernel.)
// ---------------------------------------------------------------------------
__global__ void __launch_bounds__(256) entmax_tau_kernel() {
    __shared__ float smx[8];
    __shared__ float sm[2][16];

    const size_t row  = blockIdx.x;
    const float4* rowp = (const float4*)(g_scores + row * S_);
    const int    tid  = threadIdx.x;
    const int    lane = tid & 31;
    const int    wid  = tid >> 5;

    float4 xv = rowp[tid];

    float m = fmaxf(fmaxf(xv.x, xv.y), fmaxf(xv.z, xv.w));
    #pragma unroll
    for (int o = 16; o; o >>= 1) m = fmaxf(m, __shfl_xor_sync(0xffffffffu, m, o));
    if (lane == 0) smx[wid] = m;
    __syncthreads();
    float rowmax = smx[0];
    #pragma unroll
    for (int w = 1; w < 8; ++w) rowmax = fmaxf(rowmax, smx[w]);

    float x0 = (xv.x - rowmax) * 0.5f;
    float x1 = (xv.y - rowmax) * 0.5f;
    float x2 = (xv.z - rowmax) * 0.5f;
    float x3 = (xv.w - rowmax) * 0.5f;

    // Newton on f(tau) = sum clip(x - tau)^2 - 1; root in [-1, -1/32].
    float tau = -1.0f;
    for (int it = 0; it < 20; ++it) {
        float t0 = fmaxf(x0 - tau, 0.0f);
        float t1 = fmaxf(x1 - tau, 0.0f);
        float t2 = fmaxf(x2 - tau, 0.0f);
        float t3 = fmaxf(x3 - tau, 0.0f);
        float s1 = (t0 + t1) + (t2 + t3);
        float s2 = fmaf(t0, t0, t1 * t1) + fmaf(t2, t2, t3 * t3);
        #pragma unroll
        for (int o = 16; o; o >>= 1) {
            s1 += __shfl_xor_sync(0xffffffffu, s1, o);
            s2 += __shfl_xor_sync(0xffffffffu, s2, o);
        }
        const int p = it & 1;
        if (lane == 0) { sm[p][wid] = s1; sm[p][8 + wid] = s2; }
        __syncthreads();
        float S1 = 0.0f, S2 = 0.0f;
        #pragma unroll
        for (int w = 0; w < 8; ++w) { S1 += sm[p][w]; S2 += sm[p][8 + w]; }
        tau += (S2 - 1.0f) / (2.0f * S1);
        tau  = fminf(tau, -0.03125f);          // tau* <= -1/32 provably
        if (fabsf(S2 - 1.0f) < 1e-7f) break;   // uniform across block
    }

    if (tid == 0) g_thresh[row] = rowmax + 2.0f * tau;
}

// ---------------------------------------------------------------------------
// Kernel 3: out = P V with P reconstructed on the fly from scores + threshold.
// p = max((s - T)/2, 0)^2.  128(M) x 128(N=D) tile, BK=8 over 1024 keys.
// ---------------------------------------------------------------------------
__global__ void __launch_bounds__(256) pv_kernel(const float* __restrict__ v,
                                                 float* __restrict__ out) {
    __shared__ float ps[8][132];   // [kx][m]  (transposed P tile, already squared)
    __shared__ float vs[8][132];   // [kx][n]

    const int tid  = threadIdx.x;
    const int bh   = blockIdx.y;
    const int row0 = blockIdx.x << 7;
    const int ty   = tid >> 4;
    const int tx   = tid & 15;
    const int lr   = tid >> 1;        // P tile row this thread loads
    const int lc   = (tid & 1) << 2;
    const int vr   = tid >> 5;        // V tile row (0..7)
    const int vc   = (tid & 31) << 2; // V col (0..124)

    const float* prow = g_scores + ((size_t)bh * S_ + row0 + lr) * S_ + lc;
    const float  T    = g_thresh[(size_t)bh * S_ + row0 + lr];
    const float* vp   = v + ((size_t)bh * S_ + vr) * D_ + vc;

    float4 pr = *(const float4*)prow;
    float4 vv = *(const float4*)vp;

    float acc[8][8] = {};

    for (int kb = 0; kb < S_; kb += 8) {
        float t0 = fmaxf((pr.x - T) * 0.5f, 0.0f);
        float t1 = fmaxf((pr.y - T) * 0.5f, 0.0f);
        float t2 = fmaxf((pr.z - T) * 0.5f, 0.0f);
        float t3 = fmaxf((pr.w - T) * 0.5f, 0.0f);
        ps[lc + 0][lr] = t0 * t0; ps[lc + 1][lr] = t1 * t1;
        ps[lc + 2][lr] = t2 * t2; ps[lc + 3][lr] = t3 * t3;
        *(float4*)&vs[vr][vc] = vv;
        __syncthreads();

        if (kb + 8 < S_) {
            pr = *(const float4*)(prow + kb + 8);
            vv = *(const float4*)(vp + (size_t)(kb + 8) * D_);
        }

        #pragma unroll
        for (int kx = 0; kx < 8; ++kx) {
            float4 a0 = *(const float4*)&ps[kx][ty << 2];
            float4 a1 = *(const float4*)&ps[kx][64 + (ty << 2)];
            float4 b0 = *(const float4*)&vs[kx][tx << 2];
            float4 b1 = *(const float4*)&vs[kx][64 + (tx << 2)];
            float av[8] = {a0.x, a0.y, a0.z, a0.w, a1.x, a1.y, a1.z, a1.w};
            float bv[8] = {b0.x, b0.y, b0.z, b0.w, b1.x, b1.y, b1.z, b1.w};
            #pragma unroll
            for (int i = 0; i < 8; ++i)
                #pragma unroll
                for (int j = 0; j < 8; ++j)
                    acc[i][j] = fmaf(av[i], bv[j], acc[i][j]);
        }
        __syncthreads();
    }

    #pragma unroll
    for (int rg = 0; rg < 2; ++rg)
        #pragma unroll
        for (int i = 0; i < 4; ++i) {
            int ii = row0 + (rg << 6) + (ty << 2) + i;
            #pragma unroll
            for (int cg = 0; cg < 2; ++cg) {
                int dd = (cg << 6) + (tx << 2);
                float4 o = make_float4(acc[rg * 4 + i][cg * 4 + 0],
                                       acc[rg * 4 + i][cg * 4 + 1],
                                       acc[rg * 4 + i][cg * 4 + 2],
                                       acc[rg * 4 + i][cg * 4 + 3]);
                *(float4*)(out + ((size_t)bh * S_ + ii) * D_ + dd) = o;
            }
        }
}

// ---------------------------------------------------------------------------
extern "C" void kernel_launch(void* const* d_in, const int* in_sizes, int n_in,
                              void* d_out, int out_size) {
    (void)in_sizes; (void)n_in; (void)out_size;
    const float* q    = (const float*)d_in[0];
    const float* k    = (const float*)d_in[1];
    const float* v    = (const float*)d_in[2];
    const int*   mask = (const int*)d_in[3];
    float*       out  = (float*)d_out;

    qk_kernel<<<dim3(8, 8, BH_), 256>>>(q, k, mask);
    entmax_tau_kernel<<<BH_ * S_, 256>>>();
    pv_kernel<<<dim3(8, BH_), 256>>>(v, out);
}

// round 3
// speedup vs baseline: 1.8575x; 1.5093x over previous
#include <cuda_runtime.h>

#define NEG_INF_F (-1.0e12f)

constexpr int S_  = 1024;
constexpr int D_  = 128;
constexpr int BH_ = 32;   // B*H = 4*8

// Scratch: masked+scaled scores (134 MB) and per-row entmax threshold.
static __device__ float g_scores[(size_t)BH_ * S_ * S_];
static __device__ float g_thresh[(size_t)BH_ * S_];   // rowmax + 2*tau

// ---------------------------------------------------------------------------
// Kernel 1: scores = mask ? scale * Q K^T : -1e12
// 128x128 tile, BK=8, 256 threads, 8x8 micro-tile, double-buffered smem,
// 2 blocks/SM.
// ---------------------------------------------------------------------------
__global__ void __launch_bounds__(256, 2) qk_kernel(const float* __restrict__ q,
                                                    const float* __restrict__ k,
                                                    const int*   __restrict__ mask) {
    __shared__ float qs[2][8][132];   // [buf][kx][m], 132 keeps float4 align
    __shared__ float ks[2][8][132];   // [buf][kx][n]

    const int tid  = threadIdx.x;
    const int bh   = blockIdx.z;
    const int b    = bh >> 3;
    const int row0 = blockIdx.y << 7;
    const int col0 = blockIdx.x << 7;
    const int ty   = tid >> 4;        // 0..15
    const int tx   = tid & 15;        // 0..15
    const int lr   = tid >> 1;        // 0..127 (tile row to load)
    const int lc   = (tid & 1) << 2;  // 0 or 4

    const float* qp = q + ((size_t)bh * S_ + row0 + lr) * D_ + lc;
    const float* kp = k + ((size_t)bh * S_ + col0 + lr) * D_ + lc;

    float4 qreg = *(const float4*)qp;
    float4 kreg = *(const float4*)kp;

    qs[0][lc + 0][lr] = qreg.x; qs[0][lc + 1][lr] = qreg.y;
    qs[0][lc + 2][lr] = qreg.z; qs[0][lc + 3][lr] = qreg.w;
    ks[0][lc + 0][lr] = kreg.x; ks[0][lc + 1][lr] = kreg.y;
    ks[0][lc + 2][lr] = kreg.z; ks[0][lc + 3][lr] = kreg.w;
    __syncthreads();

    float acc[8][8] = {};
    constexpr int NC = D_ / 8;   // 16 chunks

    for (int c = 0; c < NC; ++c) {
        const int cur = c & 1;
        if (c + 1 < NC) {
            qreg = *(const float4*)(qp + (c + 1) * 8);
            kreg = *(const float4*)(kp + (c + 1) * 8);
        }

        #pragma unroll
        for (int kx = 0; kx < 8; ++kx) {
            float4 a0 = *(const float4*)&qs[cur][kx][ty << 2];
            float4 a1 = *(const float4*)&qs[cur][kx][64 + (ty << 2)];
            float4 b0 = *(const float4*)&ks[cur][kx][tx << 2];
            float4 b1 = *(const float4*)&ks[cur][kx][64 + (tx << 2)];
            float av[8] = {a0.x, a0.y, a0.z, a0.w, a1.x, a1.y, a1.z, a1.w};
            float bv[8] = {b0.x, b0.y, b0.z, b0.w, b1.x, b1.y, b1.z, b1.w};
            #pragma unroll
            for (int i = 0; i < 8; ++i)
                #pragma unroll
                for (int j = 0; j < 8; ++j)
                    acc[i][j] = fmaf(av[i], bv[j], acc[i][j]);
        }

        if (c + 1 < NC) {
            const int nxt = cur ^ 1;
            qs[nxt][lc + 0][lr] = qreg.x; qs[nxt][lc + 1][lr] = qreg.y;
            qs[nxt][lc + 2][lr] = qreg.z; qs[nxt][lc + 3][lr] = qreg.w;
            ks[nxt][lc + 0][lr] = kreg.x; ks[nxt][lc + 1][lr] = kreg.y;
            ks[nxt][lc + 2][lr] = kreg.z; ks[nxt][lc + 3][lr] = kreg.w;
        }
        __syncthreads();
    }

    const float scale = 0.08838834764831845f;   // 1/sqrt(128)
    float*     srow = g_scores + (size_t)bh * S_ * S_;
    const int* mrow = mask     + (size_t)b  * S_ * S_;

    #pragma unroll
    for (int rg = 0; rg < 2; ++rg)
        #pragma unroll
        for (int i = 0; i < 4; ++i) {
            int ii = row0 + (rg << 6) + (ty << 2) + i;
            #pragma unroll
            for (int cg = 0; cg < 2; ++cg) {
                int jj = col0 + (cg << 6) + (tx << 2);
                int4 mk = *(const int4*)(mrow + (size_t)ii * S_ + jj);
                float4 o;
                o.x = mk.x ? acc[rg * 4 + i][cg * 4 + 0] * scale : NEG_INF_F;
                o.y = mk.y ? acc[rg * 4 + i][cg * 4 + 1] * scale : NEG_INF_F;
                o.z = mk.z ? acc[rg * 4 + i][cg * 4 + 2] * scale : NEG_INF_F;
                o.w = mk.w ? acc[rg * 4 + i][cg * 4 + 3] * scale : NEG_INF_F;
                *(float4*)(srow + (size_t)ii * S_ + jj) = o;
            }
        }
}

// ---------------------------------------------------------------------------
// Kernel 2: per-row entmax-1.5 threshold, one WARP per row (no block syncs).
// Solve sum(max((s-rowmax)/2 - tau, 0)^2) = 1 via safeguarded Newton; write
// T = rowmax + 2*tau.  Row (1024 floats) lives in 32 registers per lane.
// ---------------------------------------------------------------------------
__global__ void __launch_bounds__(256) entmax_tau_kernel() {
    const int tid  = threadIdx.x;
    const int lane = tid & 31;
    const int wid  = tid >> 5;
    const size_t row = (size_t)blockIdx.x * 8 + wid;

    const float4* rowp = (const float4*)(g_scores + row * S_);

    float x[32];
    float m = -3.4e38f;
    #pragma unroll
    for (int j = 0; j < 8; ++j) {
        float4 v = rowp[lane + (j << 5)];        // coalesced
        x[j * 4 + 0] = v.x; x[j * 4 + 1] = v.y;
        x[j * 4 + 2] = v.z; x[j * 4 + 3] = v.w;
        m = fmaxf(m, fmaxf(fmaxf(v.x, v.y), fmaxf(v.z, v.w)));
    }
    #pragma unroll
    for (int o = 16; o; o >>= 1) m = fmaxf(m, __shfl_xor_sync(0xffffffffu, m, o));

    #pragma unroll
    for (int e = 0; e < 32; ++e) x[e] = (x[e] - m) * 0.5f;

    // Newton on f(tau) = sum clip(x - tau)^2 - 1; root in [-1, -1/32].
    float tau = -1.0f;
    for (int it = 0; it < 20; ++it) {
        float s1 = 0.0f, s2 = 0.0f;
        #pragma unroll
        for (int e = 0; e < 32; ++e) {
            float t = fmaxf(x[e] - tau, 0.0f);
            s1 += t;
            s2 = fmaf(t, t, s2);
        }
        #pragma unroll
        for (int o = 16; o; o >>= 1) {
            s1 += __shfl_xor_sync(0xffffffffu, s1, o);
            s2 += __shfl_xor_sync(0xffffffffu, s2, o);
        }
        tau += (s2 - 1.0f) / (2.0f * s1);
        tau  = fminf(tau, -0.03125f);            // tau* <= -1/32 provably
        if (fabsf(s2 - 1.0f) < 1e-7f) break;     // warp-uniform
    }

    if (lane == 0) g_thresh[row] = m + 2.0f * tau;
}

// ---------------------------------------------------------------------------
// Kernel 3: out = P V, P reconstructed on the fly: p = max((s-T)/2, 0)^2.
// 128(M) x 128(N=D) tile, BK=8 over 1024 keys, double-buffered, 2 blocks/SM.
// ---------------------------------------------------------------------------
__global__ void __launch_bounds__(256, 2) pv_kernel(const float* __restrict__ v,
                                                    float* __restrict__ out) {
    __shared__ float ps[2][8][132];   // [buf][kx][m] (P^T tile, squared)
    __shared__ float vs[2][8][132];   // [buf][kx][n]

    const int tid  = threadIdx.x;
    const int bh   = blockIdx.y;
    const int row0 = blockIdx.x << 7;
    const int ty   = tid >> 4;
    const int tx   = tid & 15;
    const int lr   = tid >> 1;        // P tile row this thread loads
    const int lc   = (tid & 1) << 2;
    const int vr   = tid >> 5;        // V tile row (0..7)
    const int vc   = (tid & 31) << 2; // V col (0..124)

    const float* prow = g_scores + ((size_t)bh * S_ + row0 + lr) * S_ + lc;
    const float  T    = g_thresh[(size_t)bh * S_ + row0 + lr];
    const float* vp   = v + ((size_t)bh * S_ + vr) * D_ + vc;

    float4 pr = *(const float4*)prow;
    float4 vv = *(const float4*)vp;

    {
        float t0 = fmaxf((pr.x - T) * 0.5f, 0.0f);
        float t1 = fmaxf((pr.y - T) * 0.5f, 0.0f);
        float t2 = fmaxf((pr.z - T) * 0.5f, 0.0f);
        float t3 = fmaxf((pr.w - T) * 0.5f, 0.0f);
        ps[0][lc + 0][lr] = t0 * t0; ps[0][lc + 1][lr] = t1 * t1;
        ps[0][lc + 2][lr] = t2 * t2; ps[0][lc + 3][lr] = t3 * t3;
        *(float4*)&vs[0][vr][vc] = vv;
    }
    __syncthreads();

    float acc[8][8] = {};
    constexpr int NC = S_ / 8;   // 128 chunks

    for (int c = 0; c < NC; ++c) {
        const int cur = c & 1;
        if (c + 1 < NC) {
            pr = *(const float4*)(prow + (c + 1) * 8);
            vv = *(const float4*)(vp + (size_t)(c + 1) * 8 * D_);
        }

        #pragma unroll
        for (int kx = 0; kx < 8; ++kx) {
            float4 a0 = *(const float4*)&ps[cur][kx][ty << 2];
            float4 a1 = *(const float4*)&ps[cur][kx][64 + (ty << 2)];
            float4 b0 = *(const float4*)&vs[cur][kx][tx << 2];
            float4 b1 = *(const float4*)&vs[cur][kx][64 + (tx << 2)];
            float av[8] = {a0.x, a0.y, a0.z, a0.w, a1.x, a1.y, a1.z, a1.w};
            float bv[8] = {b0.x, b0.y, b0.z, b0.w, b1.x, b1.y, b1.z, b1.w};
            #pragma unroll
            for (int i = 0; i < 8; ++i)
                #pragma unroll
                for (int j = 0; j < 8; ++j)
                    acc[i][j] = fmaf(av[i], bv[j], acc[i][j]);
        }

        if (c + 1 < NC) {
            const int nxt = cur ^ 1;
            float t0 = fmaxf((pr.x - T) * 0.5f, 0.0f);
            float t1 = fmaxf((pr.y - T) * 0.5f, 0.0f);
            float t2 = fmaxf((pr.z - T) * 0.5f, 0.0f);
            float t3 = fmaxf((pr.w - T) * 0.5f, 0.0f);
            ps[nxt][lc + 0][lr] = t0 * t0; ps[nxt][lc + 1][lr] = t1 * t1;
            ps[nxt][lc + 2][lr] = t2 * t2; ps[nxt][lc + 3][lr] = t3 * t3;
            *(float4*)&vs[nxt][vr][vc] = vv;
        }
        __syncthreads();
    }

    #pragma unroll
    for (int rg = 0; rg < 2; ++rg)
        #pragma unroll
        for (int i = 0; i < 4; ++i) {
            int ii = row0 + (rg << 6) + (ty << 2) + i;
            #pragma unroll
            for (int cg = 0; cg < 2; ++cg) {
                int dd = (cg << 6) + (tx << 2);
                float4 o = make_float4(acc[rg * 4 + i][cg * 4 + 0],
                                       acc[rg * 4 + i][cg * 4 + 1],
                                       acc[rg * 4 + i][cg * 4 + 2],
                                       acc[rg * 4 + i][cg * 4 + 3]);
                *(float4*)(out + ((size_t)bh * S_ + ii) * D_ + dd) = o;
            }
        }
}

// ---------------------------------------------------------------------------
extern "C" void kernel_launch(void* const* d_in, const int* in_sizes, int n_in,
                              void* d_out, int out_size) {
    (void)in_sizes; (void)n_in; (void)out_size;
    const float* q    = (const float*)d_in[0];
    const float* k    = (const float*)d_in[1];
    const float* v    = (const float*)d_in[2];
    const int*   mask = (const int*)d_in[3];
    float*       out  = (float*)d_out;

    qk_kernel<<<dim3(8, 8, BH_), 256>>>(q, k, mask);
    entmax_tau_kernel<<<BH_ * S_ / 8, 256>>>();
    pv_kernel<<<dim3(8, BH_), 256>>>(v, out);
}

// round 4
// speedup vs baseline: 2.9589x; 1.5930x over previous
#include <cuda_runtime.h>
#include <cuda_bf16.h>
#include <cstdint>

#define NEG_INF_F (-1.0e12f)

constexpr int S_  = 1024;
constexpr int D_  = 128;
constexpr int BH_ = 32;   // B*H

// Scratch: masked+scaled scores (134 MB) and per-row entmax threshold.
static __device__ float g_scores[(size_t)BH_ * S_ * S_];
static __device__ float g_thresh[(size_t)BH_ * S_];   // rowmax + 2*tau

// ---------------------------------------------------------------------------
// PTX helpers
// ---------------------------------------------------------------------------
__device__ __forceinline__ void ldsm4(uint32_t* r, uint32_t addr) {
    asm volatile("ldmatrix.sync.aligned.m8n8.x4.shared.b16 {%0,%1,%2,%3}, [%4];\n"
                 : "=r"(r[0]), "=r"(r[1]), "=r"(r[2]), "=r"(r[3]) : "r"(addr));
}
__device__ __forceinline__ void ldsm4t(uint32_t* r, uint32_t addr) {
    asm volatile("ldmatrix.sync.aligned.m8n8.x4.trans.shared.b16 {%0,%1,%2,%3}, [%4];\n"
                 : "=r"(r[0]), "=r"(r[1]), "=r"(r[2]), "=r"(r[3]) : "r"(addr));
}
__device__ __forceinline__ void mma_bf16(float* c, const uint32_t* a,
                                         uint32_t b0, uint32_t b1) {
    asm volatile("mma.sync.aligned.m16n8k16.row.col.f32.bf16.bf16.f32 "
                 "{%0,%1,%2,%3}, {%4,%5,%6,%7}, {%8,%9}, {%0,%1,%2,%3};\n"
                 : "+f"(c[0]), "+f"(c[1]), "+f"(c[2]), "+f"(c[3])
                 : "r"(a[0]), "r"(a[1]), "r"(a[2]), "r"(a[3]), "r"(b0), "r"(b1));
}
// Split two fp32 into packed bf16 hi-plane and lo-plane words.
__device__ __forceinline__ void split2(float a, float b, uint32_t& hi, uint32_t& lo) {
    __nv_bfloat16 ha = __float2bfloat16_rn(a), hb = __float2bfloat16_rn(b);
    __nv_bfloat16 la = __float2bfloat16_rn(a - __bfloat162float(ha));
    __nv_bfloat16 lb = __float2bfloat16_rn(b - __bfloat162float(hb));
    hi = ((uint32_t)__bfloat16_as_ushort(hb) << 16) | __bfloat16_as_ushort(ha);
    lo = ((uint32_t)__bfloat16_as_ushort(lb) << 16) | __bfloat16_as_ushort(la);
}

// ---------------------------------------------------------------------------
// Kernel 1: scores = mask ? scale * Q K^T : -1e12   (bf16 hi/lo 3-way MMA)
// 128x128 tile, BK=32, 256 threads (8 warps = 4m x 2n), warp tile 32x64.
// ---------------------------------------------------------------------------
__global__ void __launch_bounds__(256) qk_kernel(const float* __restrict__ q,
                                                 const float* __restrict__ k,
                                                 const int*   __restrict__ mask) {
    __shared__ __align__(16) __nv_bfloat16 sQ[2][128][40];   // [plane][m][k] pad->40
    __shared__ __align__(16) __nv_bfloat16 sK[2][128][40];   // [plane][n][k]

    const int tid  = threadIdx.x;
    const int lane = tid & 31;
    const int wid  = tid >> 5;
    const int wm   = wid & 3;          // 4 m-slabs of 32
    const int wn   = wid >> 2;         // 2 n-slabs of 64
    const int bh   = blockIdx.z;
    const int b    = bh >> 3;
    const int row0 = blockIdx.y << 7;
    const int col0 = blockIdx.x << 7;

    // gmem load mapping: per chunk, 4 float4 per thread per matrix
    const int grow = tid >> 3;                  // 0..31 (+32j)
    const int gcol = (tid & 7) << 2;            // 0..28
    const float* qp = q + ((size_t)bh * S_ + row0 + grow) * D_ + gcol;
    const float* kp = k + ((size_t)bh * S_ + col0 + grow) * D_ + gcol;

    // ldmatrix addresses
    const uint32_t sQa = (uint32_t)__cvta_generic_to_shared(&sQ[0][0][0]);
    const uint32_t sKa = (uint32_t)__cvta_generic_to_shared(&sK[0][0][0]);
    const int lrA = lane & 15, lcA = (lane >> 4) << 3;
    const int lrB = ((lane >> 4) << 3) + (lane & 7), lcB = ((lane >> 3) & 1) << 3;
    uint32_t aAddr[2][2], bAddr[2][4];
    #pragma unroll
    for (int p = 0; p < 2; ++p) {
        #pragma unroll
        for (int mi = 0; mi < 2; ++mi)
            aAddr[p][mi] = sQa + 2u * ((p * 128 + wm * 32 + mi * 16 + lrA) * 40 + lcA);
        #pragma unroll
        for (int ntp = 0; ntp < 4; ++ntp)
            bAddr[p][ntp] = sKa + 2u * ((p * 128 + wn * 64 + ntp * 16 + lrB) * 40 + lcB);
    }

    float acc[2][8][4] = {};
    float4 pq[4], pk[4];

    #pragma unroll
    for (int j = 0; j < 4; ++j) {
        pq[j] = *(const float4*)(qp + (size_t)(32 * j) * D_);
        pk[j] = *(const float4*)(kp + (size_t)(32 * j) * D_);
    }

    constexpr int NC = D_ / 32;   // 4 chunks
    for (int c = 0; c < NC; ++c) {
        #pragma unroll
        for (int j = 0; j < 4; ++j) {
            int r = grow + 32 * j;
            uint32_t h0, l0, h1, l1;
            split2(pq[j].x, pq[j].y, h0, l0);
            split2(pq[j].z, pq[j].w, h1, l1);
            *(uint2*)&sQ[0][r][gcol] = make_uint2(h0, h1);
            *(uint2*)&sQ[1][r][gcol] = make_uint2(l0, l1);
            split2(pk[j].x, pk[j].y, h0, l0);
            split2(pk[j].z, pk[j].w, h1, l1);
            *(uint2*)&sK[0][r][gcol] = make_uint2(h0, h1);
            *(uint2*)&sK[1][r][gcol] = make_uint2(l0, l1);
        }
        __syncthreads();

        if (c + 1 < NC) {
            #pragma unroll
            for (int j = 0; j < 4; ++j) {
                pq[j] = *(const float4*)(qp + (size_t)(32 * j) * D_ + (c + 1) * 32);
                pk[j] = *(const float4*)(kp + (size_t)(32 * j) * D_ + (c + 1) * 32);
            }
        }

        #pragma unroll
        for (int kk = 0; kk < 2; ++kk) {
            uint32_t Ah[2][4], Al[2][4];
            ldsm4(Ah[0], aAddr[0][0] + 32 * kk);
            ldsm4(Ah[1], aAddr[0][1] + 32 * kk);
            ldsm4(Al[0], aAddr[1][0] + 32 * kk);
            ldsm4(Al[1], aAddr[1][1] + 32 * kk);
            #pragma unroll
            for (int ntp = 0; ntp < 4; ++ntp) {
                uint32_t Bh[4], Bl[4];
                ldsm4(Bh, bAddr[0][ntp] + 32 * kk);
                ldsm4(Bl, bAddr[1][ntp] + 32 * kk);
                #pragma unroll
                for (int mi = 0; mi < 2; ++mi)
                    #pragma unroll
                    for (int nt = 0; nt < 2; ++nt) {
                        float* cacc = acc[mi][ntp * 2 + nt];
                        mma_bf16(cacc, Ah[mi], Bh[2 * nt], Bh[2 * nt + 1]);
                        mma_bf16(cacc, Ah[mi], Bl[2 * nt], Bl[2 * nt + 1]);
                        mma_bf16(cacc, Al[mi], Bh[2 * nt], Bh[2 * nt + 1]);
                    }
            }
        }
        __syncthreads();
    }

    const float scale = 0.08838834764831845f;   // 1/sqrt(128)
    float*     srow = g_scores + (size_t)bh * S_ * S_;
    const int* mrow = mask     + (size_t)b  * S_ * S_;
    const int  rb   = row0 + wm * 32 + (lane >> 2);
    const int  cb   = col0 + wn * 64 + ((lane & 3) << 1);

    #pragma unroll
    for (int mi = 0; mi < 2; ++mi)
        #pragma unroll
        for (int h = 0; h < 2; ++h) {
            int r = rb + mi * 16 + h * 8;
            #pragma unroll
            for (int ni = 0; ni < 8; ++ni) {
                int cc = cb + ni * 8;
                int2 mk = *(const int2*)(mrow + (size_t)r * S_ + cc);
                float2 o;
                o.x = mk.x ? acc[mi][ni][2 * h]     * scale : NEG_INF_F;
                o.y = mk.y ? acc[mi][ni][2 * h + 1] * scale : NEG_INF_F;
                *(float2*)(srow + (size_t)r * S_ + cc) = o;
            }
        }
}

// ---------------------------------------------------------------------------
// Kernel 2: per-row entmax-1.5 threshold, one warp per row.
// ---------------------------------------------------------------------------
__global__ void __launch_bounds__(256) entmax_tau_kernel() {
    const int tid  = threadIdx.x;
    const int lane = tid & 31;
    const int wid  = tid >> 5;
    const size_t row = (size_t)blockIdx.x * 8 + wid;

    const float4* rowp = (const float4*)(g_scores + row * S_);

    float x[32];
    float m = -3.4e38f;
    #pragma unroll
    for (int j = 0; j < 8; ++j) {
        float4 v = rowp[lane + (j << 5)];
        x[j * 4 + 0] = v.x; x[j * 4 + 1] = v.y;
        x[j * 4 + 2] = v.z; x[j * 4 + 3] = v.w;
        m = fmaxf(m, fmaxf(fmaxf(v.x, v.y), fmaxf(v.z, v.w)));
    }
    #pragma unroll
    for (int o = 16; o; o >>= 1) m = fmaxf(m, __shfl_xor_sync(0xffffffffu, m, o));

    #pragma unroll
    for (int e = 0; e < 32; ++e) x[e] = (x[e] - m) * 0.5f;

    float tau = -1.0f;
    for (int it = 0; it < 16; ++it) {
        float s1 = 0.0f, s2 = 0.0f;
        #pragma unroll
        for (int e = 0; e < 32; ++e) {
            float t = fmaxf(x[e] - tau, 0.0f);
            s1 += t;
            s2 = fmaf(t, t, s2);
        }
        #pragma unroll
        for (int o = 16; o; o >>= 1) {
            s1 += __shfl_xor_sync(0xffffffffu, s1, o);
            s2 += __shfl_xor_sync(0xffffffffu, s2, o);
        }
        tau += (s2 - 1.0f) / (2.0f * s1);
        tau  = fminf(tau, -0.03125f);            // tau* <= -1/32 provably
        if (fabsf(s2 - 1.0f) < 2e-6f) break;     // warp-uniform
    }

    if (lane == 0) g_thresh[row] = m + 2.0f * tau;
}

// ---------------------------------------------------------------------------
// Kernel 3: out = P V, P = max((s-T)/2,0)^2 reconstructed on the fly,
// split to bf16 hi/lo in smem; V split likewise; 3-way MMA.
// 128(M) x 128(N=D) block tile, BK=32 over 1024 keys.
// ---------------------------------------------------------------------------
__global__ void __launch_bounds__(256) pv_kernel(const float* __restrict__ v,
                                                 float* __restrict__ out) {
    __shared__ __align__(16) __nv_bfloat16 sP[2][128][40];   // [plane][m][k]
    __shared__ __align__(16) __nv_bfloat16 sV[2][32][152];   // [plane][k][n] pad->152

    const int tid  = threadIdx.x;
    const int lane = tid & 31;
    const int wid  = tid >> 5;
    const int wm   = wid & 3;
    const int wn   = wid >> 2;
    const int bh   = blockIdx.y;
    const int row0 = blockIdx.x << 7;

    // P loads: 4 float4 per thread per chunk (rows fixed per j)
    const int prow = tid >> 3;                 // 0..31 (+32j)
    const int pcol = (tid & 7) << 2;
    const float* pp = g_scores + ((size_t)bh * S_ + row0 + prow) * S_ + pcol;
    float Trow[4];
    #pragma unroll
    for (int j = 0; j < 4; ++j)
        Trow[j] = g_thresh[(size_t)bh * S_ + row0 + prow + 32 * j];

    // V loads: 4 float4 per thread per chunk
    const int vrow = tid >> 5;                 // 0..7 (+8j)
    const int vcol = (tid & 31) << 2;
    const float* vp = v + ((size_t)bh * S_ + vrow) * D_ + vcol;

    const uint32_t sPa = (uint32_t)__cvta_generic_to_shared(&sP[0][0][0]);
    const uint32_t sVa = (uint32_t)__cvta_generic_to_shared(&sV[0][0][0]);
    const int lrA = lane & 15, lcA = (lane >> 4) << 3;
    const int lrB = ((lane >> 3) & 1) * 8 + (lane & 7);     // k-row
    const int lcB = (lane >> 4) << 3;                       // n-col
    uint32_t aAddr[2][2], bAddr[2][4];
    #pragma unroll
    for (int p = 0; p < 2; ++p) {
        #pragma unroll
        for (int mi = 0; mi < 2; ++mi)
            aAddr[p][mi] = sPa + 2u * ((p * 128 + wm * 32 + mi * 16 + lrA) * 40 + lcA);
        #pragma unroll
        for (int ntp = 0; ntp < 4; ++ntp)
            bAddr[p][ntp] = sVa + 2u * ((p * 32 + lrB) * 152 + wn * 64 + ntp * 16 + lcB);
    }

    float acc[2][8][4] = {};
    float4 pr[4], pv4[4];

    #pragma unroll
    for (int j = 0; j < 4; ++j) {
        pr[j]  = *(const float4*)(pp + (size_t)(32 * j) * S_);
        pv4[j] = *(const float4*)(vp + (size_t)(8 * j) * D_);
    }

    constexpr int NC = S_ / 32;   // 32 chunks
    for (int c = 0; c < NC; ++c) {
        #pragma unroll
        for (int j = 0; j < 4; ++j) {
            // P: reconstruct probabilities, split
            float T = Trow[j];
            float t0 = fmaxf((pr[j].x - T) * 0.5f, 0.0f);
            float t1 = fmaxf((pr[j].y - T) * 0.5f, 0.0f);
            float t2 = fmaxf((pr[j].z - T) * 0.5f, 0.0f);
            float t3 = fmaxf((pr[j].w - T) * 0.5f, 0.0f);
            uint32_t h0, l0, h1, l1;
            split2(t0 * t0, t1 * t1, h0, l0);
            split2(t2 * t2, t3 * t3, h1, l1);
            int r = prow + 32 * j;
            *(uint2*)&sP[0][r][pcol] = make_uint2(h0, h1);
            *(uint2*)&sP[1][r][pcol] = make_uint2(l0, l1);
            // V split
            split2(pv4[j].x, pv4[j].y, h0, l0);
            split2(pv4[j].z, pv4[j].w, h1, l1);
            int vr = vrow + 8 * j;
            *(uint2*)&sV[0][vr][vcol] = make_uint2(h0, h1);
            *(uint2*)&sV[1][vr][vcol] = make_uint2(l0, l1);
        }
        __syncthreads();

        if (c + 1 < NC) {
            #pragma unroll
            for (int j = 0; j < 4; ++j) {
                pr[j]  = *(const float4*)(pp + (size_t)(32 * j) * S_ + (c + 1) * 32);
                pv4[j] = *(const float4*)(vp + (size_t)((c + 1) * 32 + 8 * j) * D_);
            }
        }

        #pragma unroll
        for (int kk = 0; kk < 2; ++kk) {
            uint32_t Ah[2][4], Al[2][4];
            ldsm4(Ah[0], aAddr[0][0] + 32 * kk);
            ldsm4(Ah[1], aAddr[0][1] + 32 * kk);
            ldsm4(Al[0], aAddr[1][0] + 32 * kk);
            ldsm4(Al[1], aAddr[1][1] + 32 * kk);
            #pragma unroll
            for (int ntp = 0; ntp < 4; ++ntp) {
                uint32_t Bh[4], Bl[4];
                ldsm4t(Bh, bAddr[0][ntp] + 4864 * kk);   // +16 k-rows * 152 * 2B
                ldsm4t(Bl, bAddr[1][ntp] + 4864 * kk);
                #pragma unroll
                for (int mi = 0; mi < 2; ++mi)
                    #pragma unroll
                    for (int nt = 0; nt < 2; ++nt) {
                        float* cacc = acc[mi][ntp * 2 + nt];
                        mma_bf16(cacc, Ah[mi], Bh[2 * nt], Bh[2 * nt + 1]);
                        mma_bf16(cacc, Ah[mi], Bl[2 * nt], Bl[2 * nt + 1]);
                        mma_bf16(cacc, Al[mi], Bh[2 * nt], Bh[2 * nt + 1]);
                    }
            }
        }
        __syncthreads();
    }

    const int rb = row0 + wm * 32 + (lane >> 2);
    const int cb = wn * 64 + ((lane & 3) << 1);
    #pragma unroll
    for (int mi = 0; mi < 2; ++mi)
        #pragma unroll
        for (int h = 0; h < 2; ++h) {
            int r = rb + mi * 16 + h * 8;
            #pragma unroll
            for (int ni = 0; ni < 8; ++ni) {
                int cc = cb + ni * 8;
                float2 o = make_float2(acc[mi][ni][2 * h], acc[mi][ni][2 * h + 1]);
                *(float2*)(out + ((size_t)bh * S_ + r) * D_ + cc) = o;
            }
        }
}

// ---------------------------------------------------------------------------
extern "C" void kernel_launch(void* const* d_in, const int* in_sizes, int n_in,
                              void* d_out, int out_size) {
    (void)in_sizes; (void)n_in; (void)out_size;
    const float* q    = (const float*)d_in[0];
    const float* k    = (const float*)d_in[1];
    const float* v    = (const float*)d_in[2];
    const int*   mask = (const int*)d_in[3];
    float*       out  = (float*)d_out;

    qk_kernel<<<dim3(8, 8, BH_), 256>>>(q, k, mask);
    entmax_tau_kernel<<<BH_ * S_ / 8, 256>>>();
    pv_kernel<<<dim3(8, BH_), 256>>>(v, out);
}

// round 5
// speedup vs baseline: 3.1494x; 1.0644x over previous
#include <cuda_runtime.h>
#include <cuda_bf16.h>
#include <cstdint>

#define NEG_INF_F (-1.0e12f)

constexpr int S_  = 1024;
constexpr int D_  = 128;
constexpr int BH_ = 32;   // B*H

// Scratch: masked+scaled scores (134 MB) and per-row entmax threshold.
static __device__ float g_scores[(size_t)BH_ * S_ * S_];
static __device__ float g_thresh[(size_t)BH_ * S_];   // rowmax + 2*tau

// ---------------------------------------------------------------------------
// PTX helpers
// ---------------------------------------------------------------------------
__device__ __forceinline__ void ldsm4(uint32_t* r, uint32_t addr) {
    asm volatile("ldmatrix.sync.aligned.m8n8.x4.shared.b16 {%0,%1,%2,%3}, [%4];\n"
                 : "=r"(r[0]), "=r"(r[1]), "=r"(r[2]), "=r"(r[3]) : "r"(addr));
}
__device__ __forceinline__ void ldsm4t(uint32_t* r, uint32_t addr) {
    asm volatile("ldmatrix.sync.aligned.m8n8.x4.trans.shared.b16 {%0,%1,%2,%3}, [%4];\n"
                 : "=r"(r[0]), "=r"(r[1]), "=r"(r[2]), "=r"(r[3]) : "r"(addr));
}
__device__ __forceinline__ void mma_bf16(float* c, const uint32_t* a,
                                         uint32_t b0, uint32_t b1) {
    asm volatile("mma.sync.aligned.m16n8k16.row.col.f32.bf16.bf16.f32 "
                 "{%0,%1,%2,%3}, {%4,%5,%6,%7}, {%8,%9}, {%0,%1,%2,%3};\n"
                 : "+f"(c[0]), "+f"(c[1]), "+f"(c[2]), "+f"(c[3])
                 : "r"(a[0]), "r"(a[1]), "r"(a[2]), "r"(a[3]), "r"(b0), "r"(b1));
}
__device__ __forceinline__ void split2(float a, float b, uint32_t& hi, uint32_t& lo) {
    __nv_bfloat16 ha = __float2bfloat16_rn(a), hb = __float2bfloat16_rn(b);
    __nv_bfloat16 la = __float2bfloat16_rn(a - __bfloat162float(ha));
    __nv_bfloat16 lb = __float2bfloat16_rn(b - __bfloat162float(hb));
    hi = ((uint32_t)__bfloat16_as_ushort(hb) << 16) | __bfloat16_as_ushort(ha);
    lo = ((uint32_t)__bfloat16_as_ushort(lb) << 16) | __bfloat16_as_ushort(la);
}

// ---------------------------------------------------------------------------
// Kernel 1: scores = mask ? scale * Q K^T : -1e12
// 128x128 tile, 512 threads (16 warps = 4m x 4n), warp tile 32x32, BK=32,
// bf16 hi/lo 3-pass MMA, double-buffered dynamic smem (80KB).
// ---------------------------------------------------------------------------
__global__ void __launch_bounds__(512) qk_kernel(const float* __restrict__ q,
                                                 const float* __restrict__ k,
                                                 const int*   __restrict__ mask) {
    extern __shared__ __align__(16) __nv_bfloat16 smem[];
    // layout: sQ[buf][plane][128][40], sK[buf][plane][128][40]
    __nv_bfloat16* sQ = smem;
    __nv_bfloat16* sK = smem + 2 * 2 * 128 * 40;
    constexpr uint32_t BUFB = 2u * 128 * 40 * 2;   // bytes per buf (2 planes)
    constexpr uint32_t PLNE = 128 * 40;            // elements per plane

    const int tid  = threadIdx.x;
    const int lane = tid & 31;
    const int wid  = tid >> 5;
    const int wm   = wid & 3;
    const int wn   = wid >> 2;
    const int bh   = blockIdx.z;
    const int b    = bh >> 3;
    const int row0 = blockIdx.y << 7;
    const int col0 = blockIdx.x << 7;

    const int grow = tid >> 3;            // 0..63 (+64j)
    const int gcol = (tid & 7) << 2;      // 0..28
    const float* qp = q + ((size_t)bh * S_ + row0 + grow) * D_ + gcol;
    const float* kp = k + ((size_t)bh * S_ + col0 + grow) * D_ + gcol;

    const uint32_t sQa = (uint32_t)__cvta_generic_to_shared(sQ);
    const uint32_t sKa = (uint32_t)__cvta_generic_to_shared(sK);
    const int lrA = lane & 15, lcA = (lane >> 4) << 3;
    const int lrB = ((lane >> 4) << 3) + (lane & 7), lcB = ((lane >> 3) & 1) << 3;
    uint32_t aAddr[2][2], bAddr[2][2];
    #pragma unroll
    for (int p = 0; p < 2; ++p) {
        #pragma unroll
        for (int mi = 0; mi < 2; ++mi)
            aAddr[p][mi] = sQa + 2u * (p * PLNE + (wm * 32 + mi * 16 + lrA) * 40 + lcA);
        #pragma unroll
        for (int ntp = 0; ntp < 2; ++ntp)
            bAddr[p][ntp] = sKa + 2u * (p * PLNE + (wn * 32 + ntp * 16 + lrB) * 40 + lcB);
    }

    float acc[2][4][4] = {};
    float4 pq[2], pk[2];

    #pragma unroll
    for (int j = 0; j < 2; ++j) {
        pq[j] = *(const float4*)(qp + (size_t)(64 * j) * D_);
        pk[j] = *(const float4*)(kp + (size_t)(64 * j) * D_);
    }
    // store chunk 0 into buf 0
    #pragma unroll
    for (int j = 0; j < 2; ++j) {
        int r = grow + 64 * j;
        uint32_t h0, l0, h1, l1;
        split2(pq[j].x, pq[j].y, h0, l0); split2(pq[j].z, pq[j].w, h1, l1);
        *(uint2*)&sQ[(size_t)r * 40 + gcol]        = make_uint2(h0, h1);
        *(uint2*)&sQ[PLNE + (size_t)r * 40 + gcol] = make_uint2(l0, l1);
        split2(pk[j].x, pk[j].y, h0, l0); split2(pk[j].z, pk[j].w, h1, l1);
        *(uint2*)&sK[(size_t)r * 40 + gcol]        = make_uint2(h0, h1);
        *(uint2*)&sK[PLNE + (size_t)r * 40 + gcol] = make_uint2(l0, l1);
    }
    __syncthreads();

    constexpr int NC = D_ / 32;   // 4
    for (int c = 0; c < NC; ++c) {
        const uint32_t bofs = (uint32_t)(c & 1) * BUFB;
        if (c + 1 < NC) {
            #pragma unroll
            for (int j = 0; j < 2; ++j) {
                pq[j] = *(const float4*)(qp + (size_t)(64 * j) * D_ + (c + 1) * 32);
                pk[j] = *(const float4*)(kp + (size_t)(64 * j) * D_ + (c + 1) * 32);
            }
        }

        #pragma unroll
        for (int kk = 0; kk < 2; ++kk) {
            uint32_t Ah[2][4], Al[2][4], Bh[2][4], Bl[2][4];
            ldsm4(Ah[0], aAddr[0][0] + bofs + 32 * kk);
            ldsm4(Ah[1], aAddr[0][1] + bofs + 32 * kk);
            ldsm4(Al[0], aAddr[1][0] + bofs + 32 * kk);
            ldsm4(Al[1], aAddr[1][1] + bofs + 32 * kk);
            ldsm4(Bh[0], bAddr[0][0] + bofs + 32 * kk);
            ldsm4(Bh[1], bAddr[0][1] + bofs + 32 * kk);
            ldsm4(Bl[0], bAddr[1][0] + bofs + 32 * kk);
            ldsm4(Bl[1], bAddr[1][1] + bofs + 32 * kk);
            #pragma unroll
            for (int mi = 0; mi < 2; ++mi)          // pass hh
                #pragma unroll
                for (int ni = 0; ni < 4; ++ni)
                    mma_bf16(acc[mi][ni], Ah[mi], Bh[ni >> 1][(ni & 1) * 2], Bh[ni >> 1][(ni & 1) * 2 + 1]);
            #pragma unroll
            for (int mi = 0; mi < 2; ++mi)          // pass hl
                #pragma unroll
                for (int ni = 0; ni < 4; ++ni)
                    mma_bf16(acc[mi][ni], Ah[mi], Bl[ni >> 1][(ni & 1) * 2], Bl[ni >> 1][(ni & 1) * 2 + 1]);
            #pragma unroll
            for (int mi = 0; mi < 2; ++mi)          // pass lh
                #pragma unroll
                for (int ni = 0; ni < 4; ++ni)
                    mma_bf16(acc[mi][ni], Al[mi], Bh[ni >> 1][(ni & 1) * 2], Bh[ni >> 1][(ni & 1) * 2 + 1]);
        }

        if (c + 1 < NC) {
            __nv_bfloat16* dQ = sQ + ((c + 1) & 1) * 2 * PLNE;
            __nv_bfloat16* dK = sK + ((c + 1) & 1) * 2 * PLNE;
            #pragma unroll
            for (int j = 0; j < 2; ++j) {
                int r = grow + 64 * j;
                uint32_t h0, l0, h1, l1;
                split2(pq[j].x, pq[j].y, h0, l0); split2(pq[j].z, pq[j].w, h1, l1);
                *(uint2*)&dQ[(size_t)r * 40 + gcol]        = make_uint2(h0, h1);
                *(uint2*)&dQ[PLNE + (size_t)r * 40 + gcol] = make_uint2(l0, l1);
                split2(pk[j].x, pk[j].y, h0, l0); split2(pk[j].z, pk[j].w, h1, l1);
                *(uint2*)&dK[(size_t)r * 40 + gcol]        = make_uint2(h0, h1);
                *(uint2*)&dK[PLNE + (size_t)r * 40 + gcol] = make_uint2(l0, l1);
            }
        }
        __syncthreads();
    }

    const float scale = 0.08838834764831845f;
    float*     srow = g_scores + (size_t)bh * S_ * S_;
    const int* mrow = mask     + (size_t)b  * S_ * S_;
    const int  rb   = row0 + wm * 32 + (lane >> 2);
    const int  cb   = col0 + wn * 32 + ((lane & 3) << 1);

    #pragma unroll
    for (int mi = 0; mi < 2; ++mi)
        #pragma unroll
        for (int h = 0; h < 2; ++h) {
            int r = rb + mi * 16 + h * 8;
            #pragma unroll
            for (int ni = 0; ni < 4; ++ni) {
                int cc = cb + ni * 8;
                int2 mk = *(const int2*)(mrow + (size_t)r * S_ + cc);
                float2 o;
                o.x = mk.x ? acc[mi][ni][2 * h]     * scale : NEG_INF_F;
                o.y = mk.y ? acc[mi][ni][2 * h + 1] * scale : NEG_INF_F;
                *(float2*)(srow + (size_t)r * S_ + cc) = o;
            }
        }
}

// ---------------------------------------------------------------------------
// Kernel 2: per-row entmax-1.5 threshold, one warp per row.
// ---------------------------------------------------------------------------
__global__ void __launch_bounds__(256) entmax_tau_kernel() {
    const int tid  = threadIdx.x;
    const int lane = tid & 31;
    const int wid  = tid >> 5;
    const size_t row = (size_t)blockIdx.x * 8 + wid;

    const float4* rowp = (const float4*)(g_scores + row * S_);

    float x[32];
    float m = -3.4e38f;
    #pragma unroll
    for (int j = 0; j < 8; ++j) {
        float4 v = rowp[lane + (j << 5)];
        x[j * 4 + 0] = v.x; x[j * 4 + 1] = v.y;
        x[j * 4 + 2] = v.z; x[j * 4 + 3] = v.w;
        m = fmaxf(m, fmaxf(fmaxf(v.x, v.y), fmaxf(v.z, v.w)));
    }
    #pragma unroll
    for (int o = 16; o; o >>= 1) m = fmaxf(m, __shfl_xor_sync(0xffffffffu, m, o));

    #pragma unroll
    for (int e = 0; e < 32; ++e) x[e] = (x[e] - m) * 0.5f;

    float tau = -1.0f;
    for (int it = 0; it < 16; ++it) {
        float s1 = 0.0f, s2 = 0.0f;
        #pragma unroll
        for (int e = 0; e < 32; ++e) {
            float t = fmaxf(x[e] - tau, 0.0f);
            s1 += t;
            s2 = fmaf(t, t, s2);
        }
        #pragma unroll
        for (int o = 16; o; o >>= 1) {
            s1 += __shfl_xor_sync(0xffffffffu, s1, o);
            s2 += __shfl_xor_sync(0xffffffffu, s2, o);
        }
        tau += (s2 - 1.0f) / (2.0f * s1);
        tau  = fminf(tau, -0.03125f);
        if (fabsf(s2 - 1.0f) < 2e-6f) break;
    }

    if (lane == 0) g_thresh[row] = m + 2.0f * tau;
}

// ---------------------------------------------------------------------------
// Kernel 3: out = P V, P = max((s-T)/2,0)^2 on the fly. 128x128 tile,
// 512 threads (4m x 4n warps), BK=32, double-buffered dynamic smem.
// ---------------------------------------------------------------------------
__global__ void __launch_bounds__(512) pv_kernel(const float* __restrict__ v,
                                                 float* __restrict__ out) {
    extern __shared__ __align__(16) __nv_bfloat16 smem[];
    __nv_bfloat16* sP = smem;                            // [buf][plane][128][40]
    __nv_bfloat16* sV = smem + 2 * 2 * 128 * 40;         // [buf][plane][32][152]
    constexpr uint32_t PLNP = 128 * 40;
    constexpr uint32_t PLNV = 32 * 152;
    constexpr uint32_t BUFPB = 2u * PLNP * 2;   // bytes
    constexpr uint32_t BUFVB = 2u * PLNV * 2;

    const int tid  = threadIdx.x;
    const int lane = tid & 31;
    const int wid  = tid >> 5;
    const int wm   = wid & 3;
    const int wn   = wid >> 2;
    const int bh   = blockIdx.y;
    const int row0 = blockIdx.x << 7;

    const int prow = tid >> 3;            // 0..63 (+64j)
    const int pcol = (tid & 7) << 2;
    const float* pp = g_scores + ((size_t)bh * S_ + row0 + prow) * S_ + pcol;
    float Trow[2];
    #pragma unroll
    for (int j = 0; j < 2; ++j)
        Trow[j] = g_thresh[(size_t)bh * S_ + row0 + prow + 64 * j];

    const int vr = tid >> 5;              // 0..15 (+16j)
    const int vc = (lane) << 2;           // 0..124
    const float* vp = v + ((size_t)bh * S_ + vr) * D_ + vc;

    const uint32_t sPa = (uint32_t)__cvta_generic_to_shared(sP);
    const uint32_t sVa = (uint32_t)__cvta_generic_to_shared(sV);
    const int lrA = lane & 15, lcA = (lane >> 4) << 3;
    const int lrB = ((lane >> 3) & 1) * 8 + (lane & 7);
    const int lcB = (lane >> 4) << 3;
    uint32_t aAddr[2][2], bAddr[2][2];
    #pragma unroll
    for (int p = 0; p < 2; ++p) {
        #pragma unroll
        for (int mi = 0; mi < 2; ++mi)
            aAddr[p][mi] = sPa + 2u * (p * PLNP + (wm * 32 + mi * 16 + lrA) * 40 + lcA);
        #pragma unroll
        for (int ntp = 0; ntp < 2; ++ntp)
            bAddr[p][ntp] = sVa + 2u * (p * PLNV + lrB * 152 + wn * 32 + ntp * 16 + lcB);
    }

    float acc[2][4][4] = {};
    float4 pr[2], pv4[2];

    #pragma unroll
    for (int j = 0; j < 2; ++j) {
        pr[j]  = *(const float4*)(pp + (size_t)(64 * j) * S_);
        pv4[j] = *(const float4*)(vp + (size_t)(16 * j) * D_);
    }
    // store chunk 0
    #pragma unroll
    for (int j = 0; j < 2; ++j) {
        float T = Trow[j];
        float t0 = fmaxf((pr[j].x - T) * 0.5f, 0.0f);
        float t1 = fmaxf((pr[j].y - T) * 0.5f, 0.0f);
        float t2 = fmaxf((pr[j].z - T) * 0.5f, 0.0f);
        float t3 = fmaxf((pr[j].w - T) * 0.5f, 0.0f);
        uint32_t h0, l0, h1, l1;
        split2(t0 * t0, t1 * t1, h0, l0); split2(t2 * t2, t3 * t3, h1, l1);
        int r = prow + 64 * j;
        *(uint2*)&sP[(size_t)r * 40 + pcol]        = make_uint2(h0, h1);
        *(uint2*)&sP[PLNP + (size_t)r * 40 + pcol] = make_uint2(l0, l1);
        split2(pv4[j].x, pv4[j].y, h0, l0); split2(pv4[j].z, pv4[j].w, h1, l1);
        int rv = vr + 16 * j;
        *(uint2*)&sV[(size_t)rv * 152 + vc]        = make_uint2(h0, h1);
        *(uint2*)&sV[PLNV + (size_t)rv * 152 + vc] = make_uint2(l0, l1);
    }
    __syncthreads();

    constexpr int NC = S_ / 32;   // 32
    for (int c = 0; c < NC; ++c) {
        const uint32_t bpo = (uint32_t)(c & 1) * BUFPB;
        const uint32_t bvo = (uint32_t)(c & 1) * BUFVB;
        if (c + 1 < NC) {
            #pragma unroll
            for (int j = 0; j < 2; ++j) {
                pr[j]  = *(const float4*)(pp + (size_t)(64 * j) * S_ + (c + 1) * 32);
                pv4[j] = *(const float4*)(vp + (size_t)((c + 1) * 32 + 16 * j) * D_);
            }
        }

        #pragma unroll
        for (int kk = 0; kk < 2; ++kk) {
            uint32_t Ah[2][4], Al[2][4], Bh[2][4], Bl[2][4];
            ldsm4(Ah[0], aAddr[0][0] + bpo + 32 * kk);
            ldsm4(Ah[1], aAddr[0][1] + bpo + 32 * kk);
            ldsm4(Al[0], aAddr[1][0] + bpo + 32 * kk);
            ldsm4(Al[1], aAddr[1][1] + bpo + 32 * kk);
            ldsm4t(Bh[0], bAddr[0][0] + bvo + 4864 * kk);   // +16 k-rows * 152 * 2B
            ldsm4t(Bh[1], bAddr[0][1] + bvo + 4864 * kk);
            ldsm4t(Bl[0], bAddr[1][0] + bvo + 4864 * kk);
            ldsm4t(Bl[1], bAddr[1][1] + bvo + 4864 * kk);
            #pragma unroll
            for (int mi = 0; mi < 2; ++mi)
                #pragma unroll
                for (int ni = 0; ni < 4; ++ni)
                    mma_bf16(acc[mi][ni], Ah[mi], Bh[ni >> 1][(ni & 1) * 2], Bh[ni >> 1][(ni & 1) * 2 + 1]);
            #pragma unroll
            for (int mi = 0; mi < 2; ++mi)
                #pragma unroll
                for (int ni = 0; ni < 4; ++ni)
                    mma_bf16(acc[mi][ni], Ah[mi], Bl[ni >> 1][(ni & 1) * 2], Bl[ni >> 1][(ni & 1) * 2 + 1]);
            #pragma unroll
            for (int mi = 0; mi < 2; ++mi)
                #pragma unroll
                for (int ni = 0; ni < 4; ++ni)
                    mma_bf16(acc[mi][ni], Al[mi], Bh[ni >> 1][(ni & 1) * 2], Bh[ni >> 1][(ni & 1) * 2 + 1]);
        }

        if (c + 1 < NC) {
            __nv_bfloat16* dP = sP + ((c + 1) & 1) * 2 * PLNP;
            __nv_bfloat16* dV = sV + ((c + 1) & 1) * 2 * PLNV;
            #pragma unroll
            for (int j = 0; j < 2; ++j) {
                float T = Trow[j];
                float t0 = fmaxf((pr[j].x - T) * 0.5f, 0.0f);
                float t1 = fmaxf((pr[j].y - T) * 0.5f, 0.0f);
                float t2 = fmaxf((pr[j].z - T) * 0.5f, 0.0f);
                float t3 = fmaxf((pr[j].w - T) * 0.5f, 0.0f);
                uint32_t h0, l0, h1, l1;
                split2(t0 * t0, t1 * t1, h0, l0); split2(t2 * t2, t3 * t3, h1, l1);
                int r = prow + 64 * j;
                *(uint2*)&dP[(size_t)r * 40 + pcol]        = make_uint2(h0, h1);
                *(uint2*)&dP[PLNP + (size_t)r * 40 + pcol] = make_uint2(l0, l1);
                split2(pv4[j].x, pv4[j].y, h0, l0); split2(pv4[j].z, pv4[j].w, h1, l1);
                int rv = vr + 16 * j;
                *(uint2*)&dV[(size_t)rv * 152 + vc]        = make_uint2(h0, h1);
                *(uint2*)&dV[PLNV + (size_t)rv * 152 + vc] = make_uint2(l0, l1);
            }
        }
        __syncthreads();
    }

    const int rb = row0 + wm * 32 + (lane >> 2);
    const int cb = wn * 32 + ((lane & 3) << 1);
    #pragma unroll
    for (int mi = 0; mi < 2; ++mi)
        #pragma unroll
        for (int h = 0; h < 2; ++h) {
            int r = rb + mi * 16 + h * 8;
            #pragma unroll
            for (int ni = 0; ni < 4; ++ni) {
                int cc = cb + ni * 8;
                float2 o = make_float2(acc[mi][ni][2 * h], acc[mi][ni][2 * h + 1]);
                *(float2*)(out + ((size_t)bh * S_ + r) * D_ + cc) = o;
            }
        }
}

// ---------------------------------------------------------------------------
extern "C" void kernel_launch(void* const* d_in, const int* in_sizes, int n_in,
                              void* d_out, int out_size) {
    (void)in_sizes; (void)n_in; (void)out_size;
    const float* q    = (const float*)d_in[0];
    const float* k    = (const float*)d_in[1];
    const float* v    = (const float*)d_in[2];
    const int*   mask = (const int*)d_in[3];
    float*       out  = (float*)d_out;

    constexpr int QK_SMEM = 2 * 2 * 128 * 40 * 2 * 2;                 // 81920 B
    constexpr int PV_SMEM = (2 * 2 * 128 * 40 + 2 * 2 * 32 * 152) * 2; // 79872 B
    cudaFuncSetAttribute(qk_kernel, cudaFuncAttributeMaxDynamicSharedMemorySize, QK_SMEM);
    cudaFuncSetAttribute(pv_kernel, cudaFuncAttributeMaxDynamicSharedMemorySize, PV_SMEM);

    qk_kernel<<<dim3(8, 8, BH_), 512, QK_SMEM>>>(q, k, mask);
    entmax_tau_kernel<<<BH_ * S_ / 8, 256>>>();
    pv_kernel<<<dim3(8, BH_), 512, PV_SMEM>>>(v, out);
}

// round 7
// speedup vs baseline: 3.2645x; 1.0365x over previous
#include <cuda_runtime.h>
#include <cuda_bf16.h>
#include <cstdint>

#define NEG_INF_F (-1.0e12f)

constexpr int S_  = 1024;
constexpr int D_  = 128;
constexpr int BH_ = 32;   // B*H

static __device__ float g_scores[(size_t)BH_ * S_ * S_];
static __device__ float g_thresh[(size_t)BH_ * S_];   // rowmax + 2*tau

// ---------------------------------------------------------------------------
// PTX helpers
// ---------------------------------------------------------------------------
__device__ __forceinline__ void ldsm4(uint32_t* r, uint32_t addr) {
    asm volatile("ldmatrix.sync.aligned.m8n8.x4.shared.b16 {%0,%1,%2,%3}, [%4];\n"
                 : "=r"(r[0]), "=r"(r[1]), "=r"(r[2]), "=r"(r[3]) : "r"(addr));
}
__device__ __forceinline__ void ldsm4t(uint32_t* r, uint32_t addr) {
    asm volatile("ldmatrix.sync.aligned.m8n8.x4.trans.shared.b16 {%0,%1,%2,%3}, [%4];\n"
                 : "=r"(r[0]), "=r"(r[1]), "=r"(r[2]), "=r"(r[3]) : "r"(addr));
}
__device__ __forceinline__ void mma_bf16(float* c, const uint32_t* a,
                                         uint32_t b0, uint32_t b1) {
    asm volatile("mma.sync.aligned.m16n8k16.row.col.f32.bf16.bf16.f32 "
                 "{%0,%1,%2,%3}, {%4,%5,%6,%7}, {%8,%9}, {%0,%1,%2,%3};\n"
                 : "+f"(c[0]), "+f"(c[1]), "+f"(c[2]), "+f"(c[3])
                 : "r"(a[0]), "r"(a[1]), "r"(a[2]), "r"(a[3]), "r"(b0), "r"(b1));
}
__device__ __forceinline__ void split2(float a, float b, uint32_t& hi, uint32_t& lo) {
    __nv_bfloat16 ha = __float2bfloat16_rn(a), hb = __float2bfloat16_rn(b);
    __nv_bfloat16 la = __float2bfloat16_rn(a - __bfloat162float(ha));
    __nv_bfloat16 lb = __float2bfloat16_rn(b - __bfloat162float(hb));
    hi = ((uint32_t)__bfloat16_as_ushort(hb) << 16) | __bfloat16_as_ushort(ha);
    lo = ((uint32_t)__bfloat16_as_ushort(lb) << 16) | __bfloat16_as_ushort(la);
}

// ---------------------------------------------------------------------------
// Kernel 1: scores = mask ? scale * Q K^T : -1e12
// 128x128 tile, 512 threads (16 warps = 4m x 4n, warp tile 32x32),
// FULL K=128 depth resident in smem (hi/lo planes, 139KB), ONE barrier,
// then a barrier-free 8-step MMA stream.
// ---------------------------------------------------------------------------
__global__ void __launch_bounds__(512) qk_kernel(const float* __restrict__ q,
                                                 const float* __restrict__ k,
                                                 const int*   __restrict__ mask) {
    extern __shared__ __align__(16) uint8_t sm[];
    // plane layout (bytes): QH 0, QL 34816, KH 69632, KL 104448 ; pitch 136 bf16
    constexpr uint32_t QH = 0, QL = 34816, KH = 69632, KL = 104448;
    const uint32_t sb = (uint32_t)__cvta_generic_to_shared(sm);

    const int tid  = threadIdx.x;
    const int lane = tid & 31;
    const int wid  = tid >> 5;
    const int wm   = wid & 3;
    const int wn   = wid >> 2;
    const int bh   = blockIdx.z;
    const int b    = bh >> 3;
    const int row0 = blockIdx.y << 7;
    const int col0 = blockIdx.x << 7;

    // ---- load + split Q(128x128) and K(128x128), fp32 -> bf16 hi/lo planes
    const int grow = tid >> 2;          // 0..127
    const int gc0  = (tid & 3) << 2;    // 0,4,8,12 (cols gc0 + 16*j)
    const float* qg = q + ((size_t)bh * S_ + row0 + grow) * D_;
    const float* kg = k + ((size_t)bh * S_ + col0 + grow) * D_;

    #pragma unroll
    for (int j = 0; j < 8; ++j) {
        int c4 = gc0 + 16 * j;
        uint32_t off = 2u * ((uint32_t)grow * 136 + c4);
        float4 vq = *(const float4*)(qg + c4);
        uint32_t h0, l0, h1, l1;
        split2(vq.x, vq.y, h0, l0); split2(vq.z, vq.w, h1, l1);
        *(uint2*)(sm + QH + off) = make_uint2(h0, h1);
        *(uint2*)(sm + QL + off) = make_uint2(l0, l1);
        float4 vk = *(const float4*)(kg + c4);
        split2(vk.x, vk.y, h0, l0); split2(vk.z, vk.w, h1, l1);
        *(uint2*)(sm + KH + off) = make_uint2(h0, h1);
        *(uint2*)(sm + KL + off) = make_uint2(l0, l1);
    }
    __syncthreads();   // the ONLY barrier before the epilogue

    // ---- ldmatrix addresses
    const int lrA = lane & 15, lcA = (lane >> 4) << 3;
    const int lrB = ((lane >> 4) << 3) + (lane & 7), lcB = ((lane >> 3) & 1) << 3;
    uint32_t aAddr[2][2], bAddr[2][2];
    #pragma unroll
    for (int p = 0; p < 2; ++p) {
        #pragma unroll
        for (int mi = 0; mi < 2; ++mi)
            aAddr[p][mi] = sb + QH + p * 34816
                         + 2u * ((uint32_t)(wm * 32 + mi * 16 + lrA) * 136 + lcA);
        #pragma unroll
        for (int nt = 0; nt < 2; ++nt)
            bAddr[p][nt] = sb + KH + p * 34816
                         + 2u * ((uint32_t)(wn * 32 + nt * 16 + lrB) * 136 + lcB);
    }

    float acc[2][4][4] = {};

    #pragma unroll
    for (int kk = 0; kk < 8; ++kk) {
        const uint32_t ko = 32u * kk;   // 16 bf16 cols = 32 bytes
        uint32_t Ah[2][4], Al[2][4], Bh[2][4], Bl[2][4];
        ldsm4(Ah[0], aAddr[0][0] + ko);
        ldsm4(Ah[1], aAddr[0][1] + ko);
        ldsm4(Al[0], aAddr[1][0] + ko);
        ldsm4(Al[1], aAddr[1][1] + ko);
        ldsm4(Bh[0], bAddr[0][0] + ko);
        ldsm4(Bh[1], bAddr[0][1] + ko);
        ldsm4(Bl[0], bAddr[1][0] + ko);
        ldsm4(Bl[1], bAddr[1][1] + ko);
        #pragma unroll
        for (int mi = 0; mi < 2; ++mi)     // hh
            #pragma unroll
            for (int ni = 0; ni < 4; ++ni)
                mma_bf16(acc[mi][ni], Ah[mi], Bh[ni >> 1][(ni & 1) * 2], Bh[ni >> 1][(ni & 1) * 2 + 1]);
        #pragma unroll
        for (int mi = 0; mi < 2; ++mi)     // hl
            #pragma unroll
            for (int ni = 0; ni < 4; ++ni)
                mma_bf16(acc[mi][ni], Ah[mi], Bl[ni >> 1][(ni & 1) * 2], Bl[ni >> 1][(ni & 1) * 2 + 1]);
        #pragma unroll
        for (int mi = 0; mi < 2; ++mi)     // lh
            #pragma unroll
            for (int ni = 0; ni < 4; ++ni)
                mma_bf16(acc[mi][ni], Al[mi], Bh[ni >> 1][(ni & 1) * 2], Bh[ni >> 1][(ni & 1) * 2 + 1]);
    }

    // ---- epilogue: mask + scale + store
    const float scale = 0.08838834764831845f;
    float*     srow = g_scores + (size_t)bh * S_ * S_;
    const int* mrow = mask     + (size_t)b  * S_ * S_;
    const int  rb   = row0 + wm * 32 + (lane >> 2);
    const int  cb   = col0 + wn * 32 + ((lane & 3) << 1);

    #pragma unroll
    for (int mi = 0; mi < 2; ++mi)
        #pragma unroll
        for (int h = 0; h < 2; ++h) {
            int r = rb + mi * 16 + h * 8;
            #pragma unroll
            for (int ni = 0; ni < 4; ++ni) {
                int cc = cb + ni * 8;
                int2 mk = *(const int2*)(mrow + (size_t)r * S_ + cc);
                float2 o;
                o.x = mk.x ? acc[mi][ni][2 * h]     * scale : NEG_INF_F;
                o.y = mk.y ? acc[mi][ni][2 * h + 1] * scale : NEG_INF_F;
                *(float2*)(srow + (size_t)r * S_ + cc) = o;
            }
        }
}

// ---------------------------------------------------------------------------
// Kernel 2: per-row entmax-1.5 threshold, one warp per row.
// ---------------------------------------------------------------------------
__global__ void __launch_bounds__(256) entmax_tau_kernel() {
    const int tid  = threadIdx.x;
    const int lane = tid & 31;
    const int wid  = tid >> 5;
    const size_t row = (size_t)blockIdx.x * 8 + wid;

    const float4* rowp = (const float4*)(g_scores + row * S_);

    float x[32];
    float m = -3.4e38f;
    #pragma unroll
    for (int j = 0; j < 8; ++j) {
        float4 v = rowp[lane + (j << 5)];
        x[j * 4 + 0] = v.x; x[j * 4 + 1] = v.y;
        x[j * 4 + 2] = v.z; x[j * 4 + 3] = v.w;
        m = fmaxf(m, fmaxf(fmaxf(v.x, v.y), fmaxf(v.z, v.w)));
    }
    #pragma unroll
    for (int o = 16; o; o >>= 1) m = fmaxf(m, __shfl_xor_sync(0xffffffffu, m, o));

    #pragma unroll
    for (int e = 0; e < 32; ++e) x[e] = (x[e] - m) * 0.5f;

    float tau = -1.0f;
    for (int it = 0; it < 16; ++it) {
        float s1 = 0.0f, s2 = 0.0f;
        #pragma unroll
        for (int e = 0; e < 32; ++e) {
            float t = fmaxf(x[e] - tau, 0.0f);
            s1 += t;
            s2 = fmaf(t, t, s2);
        }
        #pragma unroll
        for (int o = 16; o; o >>= 1) {
            s1 += __shfl_xor_sync(0xffffffffu, s1, o);
            s2 += __shfl_xor_sync(0xffffffffu, s2, o);
        }
        tau += (s2 - 1.0f) / (2.0f * s1);
        tau  = fminf(tau, -0.03125f);
        if (fabsf(s2 - 1.0f) < 2e-6f) break;
    }

    if (lane == 0) g_thresh[row] = m + 2.0f * tau;
}

// ---------------------------------------------------------------------------
// Kernel 3: out = P V, P = max((s-T)/2,0)^2 on the fly.
// 64(M) x 128(N=D) tile, 256 threads (8 warps = 2m x 4n, warp tile 32x32),
// BK=32 over 1024 keys, double-buffered smem + DISTANCE-2 register pipeline,
// 2 CTAs/SM.
// ---------------------------------------------------------------------------
__global__ void __launch_bounds__(256, 2) pv_kernel(const float* __restrict__ v,
                                                    float* __restrict__ out) {
    extern __shared__ __align__(16) uint8_t sm[];
    // per buffer (27648B): PH 0 (64x40 bf16), PL 5120, VH 10240 (32x136), VL 18944
    constexpr uint32_t PH = 0, PL = 5120, VH = 10240, VL = 18944, BUF = 27648;
    const uint32_t sb = (uint32_t)__cvta_generic_to_shared(sm);

    const int tid  = threadIdx.x;
    const int lane = tid & 31;
    const int wid  = tid >> 5;
    const int wm   = wid & 1;          // 2 m-slabs of 32
    const int wn   = wid >> 1;         // 4 n-slabs of 32
    const int bh   = blockIdx.y;
    const int row0 = blockIdx.x << 6;  // 64 query rows

    // P loads: rows pr, pr+32; cols pc..pc+3 (per chunk)
    const int pr = tid >> 3;           // 0..31
    const int pc = (tid & 7) << 2;     // 0..28
    const float* pg  = g_scores + ((size_t)bh * S_ + row0) * S_;
    const float* pp0 = pg + (size_t)pr * S_ + pc;
    const float* pp1 = pg + (size_t)(pr + 32) * S_ + pc;
    const float  T0  = g_thresh[(size_t)bh * S_ + row0 + pr];
    const float  T1  = g_thresh[(size_t)bh * S_ + row0 + pr + 32];

    // V loads: k-rows vr+8i, n-cols vc..vc+3
    const int vr = tid >> 5;           // 0..7
    const int vc = lane << 2;          // 0..124
    const float* vg = v + (size_t)bh * S_ * D_;

    float4 Pr[2][2], Vr[2][4];         // [reg set][piece]

    auto load_chunk = [&](int c, int s) {
        Pr[s][0] = *(const float4*)(pp0 + c * 32);
        Pr[s][1] = *(const float4*)(pp1 + c * 32);
        #pragma unroll
        for (int i = 0; i < 4; ++i)
            Vr[s][i] = *(const float4*)(vg + (size_t)(c * 32 + vr + 8 * i) * D_ + vc);
    };
    auto store_chunk = [&](int s, int buf) {
        uint8_t* B = sm + (uint32_t)buf * BUF;
        #pragma unroll
        for (int i = 0; i < 2; ++i) {
            float T = i ? T1 : T0;
            float4 sc = Pr[s][i];
            float t0 = fmaxf((sc.x - T) * 0.5f, 0.0f);
            float t1 = fmaxf((sc.y - T) * 0.5f, 0.0f);
            float t2 = fmaxf((sc.z - T) * 0.5f, 0.0f);
            float t3 = fmaxf((sc.w - T) * 0.5f, 0.0f);
            uint32_t h0, l0, h1, l1;
            split2(t0 * t0, t1 * t1, h0, l0);
            split2(t2 * t2, t3 * t3, h1, l1);
            uint32_t off = 2u * ((uint32_t)(pr + 32 * i) * 40 + pc);
            *(uint2*)(B + PH + off) = make_uint2(h0, h1);
            *(uint2*)(B + PL + off) = make_uint2(l0, l1);
        }
        #pragma unroll
        for (int i = 0; i < 4; ++i) {
            float4 vv = Vr[s][i];
            uint32_t h0, l0, h1, l1;
            split2(vv.x, vv.y, h0, l0);
            split2(vv.z, vv.w, h1, l1);
            uint32_t off = 2u * ((uint32_t)(vr + 8 * i) * 136 + vc);
            *(uint2*)(B + VH + off) = make_uint2(h0, h1);
            *(uint2*)(B + VL + off) = make_uint2(l0, l1);
        }
    };

    // ldmatrix addresses (buffer 0; add buf*BUF)
    const int lrA = lane & 15, lcA = (lane >> 4) << 3;
    const int lrB = ((lane >> 3) & 1) * 8 + (lane & 7);   // k-row within 16
    const int lcB = (lane >> 4) << 3;                     // n-col offset
    uint32_t aAddr[2][2], bAddr[2][2];
    #pragma unroll
    for (int p = 0; p < 2; ++p) {
        #pragma unroll
        for (int mi = 0; mi < 2; ++mi)
            aAddr[p][mi] = sb + PH + p * 5120
                         + 2u * ((uint32_t)(wm * 32 + mi * 16 + lrA) * 40 + lcA);
        #pragma unroll
        for (int nt = 0; nt < 2; ++nt)
            bAddr[p][nt] = sb + VH + p * 8704
                         + 2u * ((uint32_t)lrB * 136 + wn * 32 + nt * 16 + lcB);
    }

    // ---- pipeline preamble
    load_chunk(0, 0);
    store_chunk(0, 0);
    load_chunk(1, 1);
    __syncthreads();

    float acc[2][4][4] = {};
    constexpr int NC = S_ / 32;    // 32 chunks

    #pragma unroll 2
    for (int c = 0; c < NC; ++c) {
        const int buf = c & 1;
        if (c + 2 < NC) load_chunk(c + 2, buf);   // set `buf` is free (chunk c already in smem)

        const uint32_t bo = (uint32_t)buf * BUF;
        #pragma unroll
        for (int kk = 0; kk < 2; ++kk) {
            const uint32_t koA = 32u * kk;        // A: +16 cols
            const uint32_t koB = 4352u * kk;      // B: +16 k-rows (16*136*2)
            uint32_t Ah[2][4], Al[2][4], Bh[2][4], Bl[2][4];
            ldsm4(Ah[0], aAddr[0][0] + bo + koA);
            ldsm4(Ah[1], aAddr[0][1] + bo + koA);
            ldsm4(Al[0], aAddr[1][0] + bo + koA);
            ldsm4(Al[1], aAddr[1][1] + bo + koA);
            ldsm4t(Bh[0], bAddr[0][0] + bo + koB);
            ldsm4t(Bh[1], bAddr[0][1] + bo + koB);
            ldsm4t(Bl[0], bAddr[1][0] + bo + koB);
            ldsm4t(Bl[1], bAddr[1][1] + bo + koB);
            #pragma unroll
            for (int mi = 0; mi < 2; ++mi)
                #pragma unroll
                for (int ni = 0; ni < 4; ++ni)
                    mma_bf16(acc[mi][ni], Ah[mi], Bh[ni >> 1][(ni & 1) * 2], Bh[ni >> 1][(ni & 1) * 2 + 1]);
            #pragma unroll
            for (int mi = 0; mi < 2; ++mi)
                #pragma unroll
                for (int ni = 0; ni < 4; ++ni)
                    mma_bf16(acc[mi][ni], Ah[mi], Bl[ni >> 1][(ni & 1) * 2], Bl[ni >> 1][(ni & 1) * 2 + 1]);
            #pragma unroll
            for (int mi = 0; mi < 2; ++mi)
                #pragma unroll
                for (int ni = 0; ni < 4; ++ni)
                    mma_bf16(acc[mi][ni], Al[mi], Bh[ni >> 1][(ni & 1) * 2], Bh[ni >> 1][(ni & 1) * 2 + 1]);
        }

        if (c + 1 < NC) store_chunk((c + 1) & 1, (c + 1) & 1);
        __syncthreads();
    }

    // ---- epilogue
    const int rb = row0 + wm * 32 + (lane >> 2);
    const int cb = wn * 32 + ((lane & 3) << 1);
    #pragma unroll
    for (int mi = 0; mi < 2; ++mi)
        #pragma unroll
        for (int h = 0; h < 2; ++h) {
            int r = rb + mi * 16 + h * 8;
            #pragma unroll
            for (int ni = 0; ni < 4; ++ni) {
                float2 o = make_float2(acc[mi][ni][2 * h], acc[mi][ni][2 * h + 1]);
                *(float2*)(out + ((size_t)bh * S_ + r) * D_ + cb + ni * 8) = o;
            }
        }
}

// ---------------------------------------------------------------------------
extern "C" void kernel_launch(void* const* d_in, const int* in_sizes, int n_in,
                              void* d_out, int out_size) {
    (void)in_sizes; (void)n_in; (void)out_size;
    const float* q    = (const float*)d_in[0];
    const float* k    = (const float*)d_in[1];
    const float* v    = (const float*)d_in[2];
    const int*   mask = (const int*)d_in[3];
    float*       out  = (float*)d_out;

    constexpr int QK_SMEM = 139264;   // 4 planes of 128x136 bf16
    constexpr int PV_SMEM = 55296;    // 2 buffers of 27648B
    cudaFuncSetAttribute(qk_kernel, cudaFuncAttributeMaxDynamicSharedMemorySize, QK_SMEM);
    cudaFuncSetAttribute(pv_kernel, cudaFuncAttributeMaxDynamicSharedMemorySize, PV_SMEM);

    qk_kernel<<<dim3(8, 8, BH_), 512, QK_SMEM>>>(q, k, mask);
    entmax_tau_kernel<<<BH_ * S_ / 8, 256>>>();
    pv_kernel<<<dim3(16, BH_), 256, PV_SMEM>>>(v, out);
}